// round 9
// baseline (speedup 1.0000x reference)
#include <cuda_runtime.h>
#include <math.h>

#define NB 8
#define NGT 100
#define NC 80
#define T_TOTAL 13343
#define K2_T 256            // 8 warps per block

__device__ __forceinline__ float neg_term(float v) {
    float cp = fminf(fmaxf(v, 1e-6f), 1.0f - 1e-6f);
    return (0.75f * (cp * cp)) * (-__logf(1.0f - cp));
}

// ---------------------------------------------------------------------------
// Fused kernel: block per (batch, gt-box), 8 warps.
// s_neg computed LAZILY per masked cell (only ~22K cells touched chip-wide,
// ~7MB instead of the 34MB eager pass). Warp per masked cell:
//   - lanes load classes lane / lane+32 / lane+64(<16): coalesced
//   - butterfly-reduce neg-focal sum; cp[label] via one shuffle
//   - broadcast float4 regr load; lane 0 writes per-cell value to smem
// Epilogue: warp l reduces level l's smem segment in f64; numpy argmin fold.
// ---------------------------------------------------------------------------
__global__ __launch_bounds__(K2_T) void level_select_kernel(
        const float* __restrict__ cls,
        const float4* __restrict__ regr4,
        const float* __restrict__ gt,
        float* __restrict__ out) {
    const int   fdim_[5] = {100, 50, 25, 13, 7};
    const int   ls_[5]   = {0, 10000, 12500, 13125, 13294};
    const float st_[5]   = {8.f, 16.f, 32.f, 64.f, 128.f};

    int bn   = blockIdx.x;                 // b*100 + n
    int b    = bn / NGT;
    int tid  = threadIdx.x;
    int lane = tid & 31;
    int wid  = tid >> 5;

    __shared__ float  sval[192];
    __shared__ double lvl[5];

    const float* gbox = gt + (size_t)bn * 5;
    float b0 = __ldg(gbox + 0), b1 = __ldg(gbox + 1);
    float b2 = __ldg(gbox + 2), b3 = __ldg(gbox + 3);
    int   label = (int)__ldg(gbox + 4);

    if (!((fabsf(b0) + fabsf(b1) + fabsf(b2) + fabsf(b3)) > 0.0f)) {
        if (tid == 0) out[bn] = -1.0f;
        return;
    }

    const float*  clsb = cls   + (size_t)b * T_TOTAL * NC;
    const float4* regb = regr4 + (size_t)b * T_TOTAL;

    // all 5 center-sampling rects (exact f32 replica of the reference)
    int rx1[5], ry1[5], rnx[5], rcnt[5];
    #pragma unroll
    for (int k = 0; k < 5; k++) {
        float stride = st_[k];
        int   fw = fdim_[k];
        float pb0 = b0 / stride, pb1 = b1 / stride;
        float pb2 = b2 / stride, pb3 = b3 / stride;
        float cx = (pb0 + pb2) * 0.5f, cy = (pb1 + pb3) * 0.5f;
        float hw = ((pb2 - pb0) * 0.2f) * 0.5f;
        float hh = ((pb3 - pb1) * 0.2f) * 0.5f;
        int x1 = (int)fminf(fmaxf(floorf(cx - hw), 0.0f), (float)(fw - 1));
        int y1 = (int)fminf(fmaxf(floorf(cy - hh), 0.0f), (float)(fw - 1));
        int x2 = min(max((int)ceilf(cx + hw), x1 + 1), fw);
        int y2 = min(max((int)ceilf(cy + hh), y1 + 1), fw);
        rx1[k] = x1; ry1[k] = y1;
        rnx[k] = x2 - x1;
        rcnt[k] = (x2 - x1) * (y2 - y1);
    }
    int total = rcnt[0] + rcnt[1] + rcnt[2] + rcnt[3] + rcnt[4];

    int lab_src = label & 31;   // lane holding the label class
    int lab_sel = label >> 5;   // which of the 3 per-lane loads

    // warp per masked cell, strided by 8 warps
    for (int idx = wid; idx < total; idx += K2_T / 32) {
        // map idx -> (level l, level-local cell c)
        int l = -1, c = idx;
        #pragma unroll
        for (int k = 0; k < 5; k++)
            if (l < 0) { if (c < rcnt[k]) l = k; else c -= rcnt[k]; }

        int nx = rnx[l];
        int x  = rx1[l] + c % nx;
        int y  = ry1[l] + c / nx;
        int t  = ls_[l] + y * fdim_[l] + x;
        float stride = st_[l];

        const float* cp_base = clsb + (size_t)t * NC;
        float a  = cp_base[lane];                    // coalesced
        float bb = cp_base[lane + 32];               // coalesced
        float cc = (lane < 16) ? cp_base[lane + 64] : 0.0f;
        float4 r = regb[t];                          // broadcast (same addr)

        // per-lane neg-focal partials, butterfly reduce -> all lanes
        float s = neg_term(a) + neg_term(bb);
        if (lane < 16) s += neg_term(cc);
        #pragma unroll
        for (int o = 16; o; o >>= 1) s += __shfl_xor_sync(0xffffffffu, s, o);

        // cp[label]: one shuffle from the owning lane
        float mine = (lab_sel == 0) ? a : ((lab_sel == 1) ? bb : cc);
        float cpl  = __shfl_sync(0xffffffffu, mine, lab_src);

        if (lane == 0) {
            float cp = fminf(fmaxf(cpl, 1e-6f), 1.0f - 1e-6f);
            float om = 1.0f - cp;
            float neg_lab = (0.75f * (cp * cp)) * (-logf(om));
            float pos_lab = (0.25f * (om * om)) * (-logf(cp));

            float sx = ((float)x + 0.5f) * stride;
            float sy = ((float)y + 0.5f) * stride;
            float tl = (sx - b0) * 0.25f, tt = (sy - b1) * 0.25f;
            float tr = (b2 - sx) * 0.25f, tb = (b3 - sy) * 0.25f;
            float t_area = (tl + tr) * (tt + tb);
            float p_area = (r.x + r.z) * (r.y + r.w);
            float wi = fminf(r.x, tl) + fminf(r.z, tr);
            float hi = fminf(r.y, tt) + fminf(r.w, tb);
            float ai = wi * hi;
            float un = t_area + p_area - ai;
            float iou = -logf((ai + 1.0f) / (un + 1.0f));  // NaN propagates

            sval[idx] = (s - neg_lab + pos_lab) + iou;
        }
    }
    __syncthreads();

    // warp w (w<5) reduces level w's segment in f64 (fixed order)
    if (wid < 5) {
        int pre = 0;
        #pragma unroll
        for (int k = 0; k < 5; k++) if (k < wid) pre += rcnt[k];
        int cnt = rcnt[wid];
        double s = 0.0;
        for (int i = lane; i < cnt; i += 32) s += (double)sval[pre + i];
        #pragma unroll
        for (int o = 16; o; o >>= 1) s += __shfl_down_sync(0xffffffffu, s, o);
        if (lane == 0) lvl[wid] = s / (double)cnt;
    }
    __syncthreads();

    if (tid == 0) {
        // numpy/jax argmin fold: pick if v<best, or v is NaN and best isn't.
        int    best = 0;
        double bv   = lvl[0];
        #pragma unroll
        for (int k = 1; k < 5; k++) {
            double v = lvl[k];
            if ((v < bv) || ((v != v) && (bv == bv))) { bv = v; best = k; }
        }
        out[bn] = (float)best;
    }
}

extern "C" void kernel_launch(void* const* d_in, const int* in_sizes, int n_in,
                              void* d_out, int out_size) {
    const float* cls  = (const float*)d_in[0];   // (8, 13343, 80) f32
    const float* regr = (const float*)d_in[1];   // (8, 13343, 4)  f32
    // d_in[2] = feature_shapes (compile-time constants, unused)
    const float* gt   = (const float*)d_in[3];   // (8, 100, 5)    f32
    float* out = (float*)d_out;                  // (8, 100)       f32

    level_select_kernel<<<NB * NGT, K2_T>>>(cls, (const float4*)regr, gt, out);
}

// round 10
// speedup vs baseline: 1.4867x; 1.4867x over previous
#include <cuda_runtime.h>
#include <math.h>

#define NB 8
#define NGT 100
#define NC 80
#define T_TOTAL 13343
#define NT 256              // threads per block
#define QPC 20              // float4 quads per cell (80 classes)
#define MAXC 128            // max masked cells per box (worst case ~123)
#define PADC 132            // psum row pad (132%32=4 -> spread banks)

__device__ __forceinline__ float neg_term(float v) {
    float cp = fminf(fmaxf(v, 1e-6f), 1.0f - 1e-6f);
    return (0.75f * (cp * cp)) * (-__logf(1.0f - cp));
}

// ---------------------------------------------------------------------------
// One block per (batch, gt-box). Lazy s_neg (only masked cells touched).
// Phase 1: flat (cell, quad) grid, float4 class loads -> smem partials.
// Phase 2: thread per cell combines partials + label + IoU terms.
// Phase 3: warp l reduces level l in f64; numpy argmin fold.
// ---------------------------------------------------------------------------
__global__ __launch_bounds__(NT) void level_select_kernel(
        const float* __restrict__ cls,
        const float4* __restrict__ regr4,
        const float* __restrict__ gt,
        float* __restrict__ out) {
    const int   fdim_[5] = {100, 50, 25, 13, 7};
    const int   ls_[5]   = {0, 10000, 12500, 13125, 13294};
    const float st_[5]   = {8.f, 16.f, 32.f, 64.f, 128.f};

    int bn   = blockIdx.x;                 // b*100 + n
    int b    = bn / NGT;
    int tid  = threadIdx.x;
    int lane = tid & 31;
    int wid  = tid >> 5;

    __shared__ float  psum[QPC * PADC];    // [quad][cell] partial neg-focal sums
    __shared__ float  sval[MAXC];          // per-cell total loss value
    __shared__ double lvl[5];

    const float* gbox = gt + (size_t)bn * 5;
    float b0 = __ldg(gbox + 0), b1 = __ldg(gbox + 1);
    float b2 = __ldg(gbox + 2), b3 = __ldg(gbox + 3);
    int   label = (int)__ldg(gbox + 4);

    if (!((fabsf(b0) + fabsf(b1) + fabsf(b2) + fabsf(b3)) > 0.0f)) {
        if (tid == 0) out[bn] = -1.0f;
        return;
    }

    const float*  clsb  = cls   + (size_t)b * T_TOTAL * NC;
    const float4* clsb4 = (const float4*)clsb;           // 20 quads per cell
    const float4* regb  = regr4 + (size_t)b * T_TOTAL;

    // all 5 center-sampling rects (exact f32 replica of the reference)
    int rx1[5], ry1[5], rnx[5], rcnt[5];
    #pragma unroll
    for (int k = 0; k < 5; k++) {
        float stride = st_[k];
        int   fw = fdim_[k];
        float pb0 = b0 / stride, pb1 = b1 / stride;
        float pb2 = b2 / stride, pb3 = b3 / stride;
        float cx = (pb0 + pb2) * 0.5f, cy = (pb1 + pb3) * 0.5f;
        float hw = ((pb2 - pb0) * 0.2f) * 0.5f;
        float hh = ((pb3 - pb1) * 0.2f) * 0.5f;
        int x1 = (int)fminf(fmaxf(floorf(cx - hw), 0.0f), (float)(fw - 1));
        int y1 = (int)fminf(fmaxf(floorf(cy - hh), 0.0f), (float)(fw - 1));
        int x2 = min(max((int)ceilf(cx + hw), x1 + 1), fw);
        int y2 = min(max((int)ceilf(cy + hh), y1 + 1), fw);
        rx1[k] = x1; ry1[k] = y1;
        rnx[k] = x2 - x1;
        rcnt[k] = (x2 - x1) * (y2 - y1);
    }
    int total = rcnt[0] + rcnt[1] + rcnt[2] + rcnt[3] + rcnt[4];

    // ---- Phase 1: (cell, quad) items; coalesced float4 loads, no shuffles ----
    int items = total * QPC;
    for (int i = tid; i < items; i += NT) {
        int cell = i / QPC;
        int q    = i - cell * QPC;

        int l = -1, c = cell;
        #pragma unroll
        for (int k = 0; k < 5; k++)
            if (l < 0) { if (c < rcnt[k]) l = k; else c -= rcnt[k]; }
        int nx = rnx[l];
        int x  = rx1[l] + c % nx;
        int y  = ry1[l] + c / nx;
        int t  = ls_[l] + y * fdim_[l] + x;

        float4 v = clsb4[t * QPC + q];
        psum[q * PADC + cell] =
            (neg_term(v.x) + neg_term(v.y)) + (neg_term(v.z) + neg_term(v.w));
    }
    __syncthreads();

    // ---- Phase 2: thread per cell ----
    if (tid < total) {
        int l = -1, c = tid;
        #pragma unroll
        for (int k = 0; k < 5; k++)
            if (l < 0) { if (c < rcnt[k]) l = k; else c -= rcnt[k]; }
        int nx = rnx[l];
        int x  = rx1[l] + c % nx;
        int y  = ry1[l] + c / nx;
        int t  = ls_[l] + y * fdim_[l] + x;
        float stride = st_[l];

        float  cpl = clsb[(size_t)t * NC + label];   // scattered, independent
        float4 r   = regb[t];                        // scattered, independent

        float sneg = 0.0f;
        #pragma unroll
        for (int q = 0; q < QPC; q++) sneg += psum[q * PADC + tid];

        float cp = fminf(fmaxf(cpl, 1e-6f), 1.0f - 1e-6f);
        float om = 1.0f - cp;
        float neg_lab = (0.75f * (cp * cp)) * (-logf(om));
        float pos_lab = (0.25f * (om * om)) * (-logf(cp));

        float sx = ((float)x + 0.5f) * stride;
        float sy = ((float)y + 0.5f) * stride;
        float tl = (sx - b0) * 0.25f, tt = (sy - b1) * 0.25f;
        float tr = (b2 - sx) * 0.25f, tb = (b3 - sy) * 0.25f;
        float t_area = (tl + tr) * (tt + tb);
        float p_area = (r.x + r.z) * (r.y + r.w);
        float wi = fminf(r.x, tl) + fminf(r.z, tr);
        float hi = fminf(r.y, tt) + fminf(r.w, tb);
        float ai = wi * hi;
        float un = t_area + p_area - ai;
        float iou = -logf((ai + 1.0f) / (un + 1.0f));  // NaN propagates

        sval[tid] = (sneg - neg_lab + pos_lab) + iou;
    }
    __syncthreads();

    // ---- Phase 3: warp w reduces level w's segment in f64 (fixed order) ----
    if (wid < 5) {
        int pre = 0;
        #pragma unroll
        for (int k = 0; k < 5; k++) if (k < wid) pre += rcnt[k];
        int cnt = rcnt[wid];
        double s = 0.0;
        for (int i = lane; i < cnt; i += 32) s += (double)sval[pre + i];
        #pragma unroll
        for (int o = 16; o; o >>= 1) s += __shfl_down_sync(0xffffffffu, s, o);
        if (lane == 0) lvl[wid] = s / (double)cnt;
    }
    __syncthreads();

    if (tid == 0) {
        // numpy/jax argmin fold: pick if v<best, or v is NaN and best isn't.
        int    best = 0;
        double bv   = lvl[0];
        #pragma unroll
        for (int k = 1; k < 5; k++) {
            double v = lvl[k];
            if ((v < bv) || ((v != v) && (bv == bv))) { bv = v; best = k; }
        }
        out[bn] = (float)best;
    }
}

extern "C" void kernel_launch(void* const* d_in, const int* in_sizes, int n_in,
                              void* d_out, int out_size) {
    const float* cls  = (const float*)d_in[0];   // (8, 13343, 80) f32
    const float* regr = (const float*)d_in[1];   // (8, 13343, 4)  f32
    // d_in[2] = feature_shapes (compile-time constants, unused)
    const float* gt   = (const float*)d_in[3];   // (8, 100, 5)    f32
    float* out = (float*)d_out;                  // (8, 100)       f32

    level_select_kernel<<<NB * NGT, NT>>>(cls, (const float4*)regr, gt, out);
}